// round 3
// baseline (speedup 1.0000x reference)
#include <cuda_runtime.h>
#include <cuda_bf16.h>

#define KK 26
#define DD 128
#define MM 256
#define BB 512
#define KP 28            // padded row stride for [MM x K] smem arrays
#define WPAD 129         // padded W row stride (conflict-free LDS)
#define OUTSZ (KK*DD + KK*KK)   // 4004

// per-word gradient scratch (device global: allocation-free)
__device__ float g_scratch[BB * OUTSZ];

// ---- dynamic shared memory layout (in floats) ----
#define SM_PS   0                      // [MM][KP] Ps, later Rres
#define SM_U    (SM_PS + MM*KP)        // [MM][KP] U,  later A
#define SM_V    (SM_U  + MM*KP)        // [MM][KP] V,  later B  (aliases Wsh in phase S)
#define SM_E    (SM_V  + MM*KP)        // [KK*KK]  exp(T)
#define SM_LAB  (SM_E  + KK*KK)        // [MM] int labels
#define SM_DEXP (SM_LAB + MM)          // [MM] int backward scale exponents
#define SM_CNT  (SM_DEXP + MM)         // [KK*KK] int transition counts
#define SM_TOT  (SM_CNT + KK*KK)       // 23368 floats = 93472 bytes

__global__ void __launch_bounds__(256, 2)
crf_word_kernel(const float* __restrict__ data,
                const int* __restrict__ labI,
                const float* __restrict__ Wg,
                const float* __restrict__ Tg)
{
    extern __shared__ float sm[];
    float* Ps  = sm + SM_PS;
    float* U   = sm + SM_U;
    float* V   = sm + SM_V;
    float* Wsh = sm + SM_V;            // alias: W lives here only during phase S
    float* E   = sm + SM_E;
    int*   lab  = (int*)(sm + SM_LAB);
    int*   dexp = (int*)(sm + SM_DEXP);
    int*   cnt  = (int*)(sm + SM_CNT);
    __shared__ int s_is64;

    const int t    = threadIdx.x;
    const int w    = blockIdx.x;
    const int lane = t & 31;
    const int wid  = t >> 5;

    // ---- detect labels dtype (int64 little-endian -> odd int32 words all zero) ----
    if (t == 0) s_is64 = 1;
    __syncthreads();
    if (labI[2*t + 1] != 0) atomicAnd(&s_is64, 0);

    // ---- init: E = exp(T), W -> padded smem, zero counts ----
    for (int p = t; p < KK*KK; p += 256) { E[p] = __expf(Tg[p]); cnt[p] = 0; }
    for (int p = t; p < KK*DD; p += 256) Wsh[(p / DD) * WPAD + (p % DD)] = Wg[p];
    __syncthreads();
    const int is64 = s_is64;
    for (int p = t; p < MM; p += 256)
        lab[p] = is64 ? labI[((size_t)w*MM + p) * 2] : labI[(size_t)w*MM + p];
    __syncthreads();
    if (t < MM - 1) atomicAdd(&cnt[lab[t]*KK + lab[t+1]], 1);   // exact int, deterministic

    // ---- Phase S: Ps[i][k] = exp(dot(x[i], W[k])) ----
    const float* x = data + (size_t)w * MM * DD;
    {
        const int ll = (lane < KK) ? lane : 0;
        const float* wr = Wsh + ll * WPAD;
        for (int r = 0; r < MM/8; ++r) {
            const int i = wid * (MM/8) + r;
            const float4* x4 = (const float4*)(x + (size_t)i * DD);
            float acc = 0.f;
            #pragma unroll
            for (int d4 = 0; d4 < DD/4; ++d4) {
                float4 v = __ldg(x4 + d4);                 // lane-uniform -> broadcast
                acc = fmaf(v.x, wr[4*d4+0], acc);
                acc = fmaf(v.y, wr[4*d4+1], acc);
                acc = fmaf(v.z, wr[4*d4+2], acc);
                acc = fmaf(v.w, wr[4*d4+3], acc);
            }
            if (lane < KK) Ps[i*KP + lane] = __expf(acc);
        }
    }
    __syncthreads();   // Ps done; Wsh region now free for V

    // ---- Phase DP: warp0 forward, warp1 backward (concurrent, linear domain) ----
    if (wid == 0) {
        const int ll = (lane < KK) ? lane : 0;
        float Ecol[KK];
        #pragma unroll
        for (int j = 0; j < KK; ++j) Ecol[j] = E[j*KK + ll];   // E[y', lane]
        float u = (lane < KK) ? 1.f : 0.f;
        if (lane < KK) U[lane] = 1.f;
        for (int i = 1; i < MM; ++i) {
            float tv = u * Ps[(i-1)*KP + ll];
            if (lane >= KK) tv = 0.f;
            float a0 = 0.f, a1 = 0.f;
            #pragma unroll
            for (int j = 0; j < KK; j += 2) {
                a0 = fmaf(__shfl_sync(0xffffffffu, tv, j),     Ecol[j],     a0);
                a1 = fmaf(__shfl_sync(0xffffffffu, tv, j + 1), Ecol[j + 1], a1);
            }
            float un = a0 + a1;
            unsigned mb = __reduce_max_sync(0xffffffffu, __float_as_uint(un));
            float s = __uint_as_float((254u - (mb >> 23)) << 23);   // exact 2^{127-fe}
            u = un * s;                                             // max(u) in [1,2)
            if (lane < KK) U[i*KP + lane] = u;
        }
    } else if (wid == 1) {
        const int ll = (lane < KK) ? lane : 0;
        float Erow[KK];
        #pragma unroll
        for (int j = 0; j < KK; ++j) Erow[j] = E[ll*KK + j];   // E[lane, y'']
        float v = (lane < KK) ? 1.f : 0.f;
        if (lane < KK) V[(MM-1)*KP + lane] = 1.f;
        if (lane == 0) dexp[MM-1] = 0;
        for (int i = MM - 2; i >= 0; --i) {
            float rv = v * Ps[(i+1)*KP + ll];
            if (lane >= KK) rv = 0.f;
            float a0 = 0.f, a1 = 0.f;
            #pragma unroll
            for (int j = 0; j < KK; j += 2) {
                a0 = fmaf(__shfl_sync(0xffffffffu, rv, j),     Erow[j],     a0);
                a1 = fmaf(__shfl_sync(0xffffffffu, rv, j + 1), Erow[j + 1], a1);
            }
            float vn = a0 + a1;
            unsigned mb = __reduce_max_sync(0xffffffffu, __float_as_uint(vn));
            int fe = (int)(mb >> 23);
            float s = __uint_as_float((unsigned)(254 - fe) << 23);
            v = vn * s;                      // V_i = vn * 2^{-(fe-127)}
            if (lane < KK) V[i*KP + lane] = v;
            if (lane == 0) dexp[i] = fe - 127;   // e_i (local step exponent)
        }
    }
    __syncthreads();

    // ---- Residual pass: Rres -> Ps, A -> U, B -> V (in place, per-row) ----
    {
        for (int r = 0; r < MM/8; ++r) {
            const int i = wid * (MM/8) + r;
            float u_ = 0.f, v_ = 0.f, p_ = 0.f, prod = 0.f;
            if (lane < KK) {
                u_ = U[i*KP + lane]; v_ = V[i*KP + lane]; p_ = Ps[i*KP + lane];
                prod = u_ * v_ * p_;
            }
            float z = prod;
            #pragma unroll
            for (int o = 16; o; o >>= 1) z += __shfl_xor_sync(0xffffffffu, z, o);
            float inv = 1.f / z;                        // 1 / z_i
            if (lane < KK) {
                float p1   = prod * inv;
                float oh   = (lab[i] == lane) ? 1.f : 0.f;
                Ps[i*KP + lane] = oh - p1;              // Rres
                U[i*KP + lane]  = ldexpf(u_ * p_ * inv, -dexp[i]);  // A
                V[i*KP + lane]  = p_ * v_;              // B
            }
        }
    }
    __syncthreads();

    float* outw = g_scratch + (size_t)w * OUTSZ;

    // ---- dT: counts - E .* sum_i A[i]^T B[i+1], i = 0..254 ----
    for (int p = t; p < KK*KK; p += 256) {
        const int a = p / KK, b = p % KK;
        float s0 = 0.f, s1 = 0.f;
        #pragma unroll 4
        for (int i = 0; i < MM - 2; i += 2) {
            s0 = fmaf(U[i*KP + a],     V[(i+1)*KP + b], s0);
            s1 = fmaf(U[(i+1)*KP + a], V[(i+2)*KP + b], s1);
        }
        s0 = fmaf(U[(MM-2)*KP + a], V[(MM-1)*KP + b], s0 + s1);
        outw[KK*DD + p] = (float)cnt[p] - E[p] * s0;
    }

    // ---- dw: Rres^T @ x  -> outw[0 .. K*D) ----
    {
        const int d    = t & (DD - 1);
        const int half = t >> 7;            // 0 or 1
        const int k0   = half * 13;
        float acc[13];
        #pragma unroll
        for (int j = 0; j < 13; ++j) acc[j] = 0.f;
        const float* xp = x + d;
        for (int i = 0; i < MM; ++i) {
            float xv = __ldg(xp + (size_t)i * DD);      // coalesced across lanes
            const float* rr = Ps + i*KP + k0;           // warp-uniform -> broadcast
            #pragma unroll
            for (int j = 0; j < 13; ++j) acc[j] = fmaf(rr[j], xv, acc[j]);
        }
        #pragma unroll
        for (int j = 0; j < 13; ++j) outw[(k0 + j)*DD + d] = acc[j];
    }
}

// ---- batch mean: out[o] = (1/B) * sum_w scratch[w][o], coalesced per-warp segments ----
__global__ void crf_reduce_kernel(float* __restrict__ out)
{
    const int o = blockIdx.x * blockDim.x + threadIdx.x;
    if (o >= OUTSZ) return;
    float s0 = 0.f, s1 = 0.f, s2 = 0.f, s3 = 0.f;
    const float* p = g_scratch + o;
    for (int w = 0; w < BB; w += 4) {
        s0 += p[(size_t)(w + 0) * OUTSZ];
        s1 += p[(size_t)(w + 1) * OUTSZ];
        s2 += p[(size_t)(w + 2) * OUTSZ];
        s3 += p[(size_t)(w + 3) * OUTSZ];
    }
    out[o] = ((s0 + s1) + (s2 + s3)) * (1.0f / BB);
}

extern "C" void kernel_launch(void* const* d_in, const int* in_sizes, int n_in,
                              void* d_out, int out_size)
{
    const float* data   = (const float*)d_in[0];
    const int*   labels = (const int*)d_in[1];
    const float* W      = (const float*)d_in[2];
    const float* T      = (const float*)d_in[3];
    float* out = (float*)d_out;

    const size_t smem = SM_TOT * sizeof(float);
    cudaFuncSetAttribute(crf_word_kernel,
                         cudaFuncAttributeMaxDynamicSharedMemorySize, (int)smem);
    crf_word_kernel<<<BB, 256, smem>>>(data, labels, W, T);
    crf_reduce_kernel<<<(OUTSZ + 255) / 256, 256>>>(out);
}